// round 15
// baseline (speedup 1.0000x reference)
#include <cuda_runtime.h>
#include <math.h>

#define R_MAX_F 6.0f
#define PI_F 3.14159265358979323846f
#define MAX_N 50048
#define MAX_DEG 64

// Static scratch (alloc-free rule). g_count zero at module load; k_gather
// re-zeroes after reading, so every execution starts from zero.
__device__ int g_count[MAX_N];
__device__ float4 g_edata[MAX_N * MAX_DEG];   // 51 MB (x,y,z,0) per edge

// Embedding copy: half the range per launch (placed before/after bucket).
__global__ void __launch_bounds__(256) k_emb(const int* __restrict__ Z,
                                             const float4* __restrict__ emb4,
                                             float4* __restrict__ out4,
                                             int N, int half) {
    long total = (long)N * 32;
    long start = half ? (total + 1) / 2 : 0;
    long end   = half ? total : (total + 1) / 2;
    long base = start + (long)blockIdx.x * 2048 + threadIdx.x;
#pragma unroll
    for (int k = 0; k < 8; k++) {
        long lin = base + (long)k * 256;
        if (lin < end) {
            int n = (int)(lin >> 5);
            int c = (int)(lin & 31);
            int z = Z[n];
            float4 v = make_float4(0.f, 0.f, 0.f, 0.f);
            if (z != 0) v = emb4[z * 32 + c];
            out4[(size_t)n * 40 + c] = v;
        }
    }
}

// Bucket: ONE edge per thread (at its L1tex scatter floor — do not batch).
__global__ void __launch_bounds__(256) k_bucket(const float* __restrict__ dr,
                                                const int* __restrict__ idx,
                                                int E) {
    int e = blockIdx.x * 256 + threadIdx.x;
    if (e >= E) return;
    int i = idx[e];
    int j = idx[E + e];
    if (i == j) return;

    float x = dr[3 * e + 0];
    float y = dr[3 * e + 1];
    float z = dr[3 * e + 2];

    int slot = atomicAdd(&g_count[i], 1);
    if (slot < MAX_DEG)
        g_edata[(i << 6) + slot] = make_float4(x, y, z, 0.0f);
}

// Per-edge accumulate: RAW moment sums (constants factored out post-reduction).
// acc[0..2]=Σuy,Σuz,Σux  acc[3..5]=Σxy,Σyz,Σxz  acc[6..8]=Σx²,Σy²,Σz²
// acc[9..15]=raw cubics  acc[16..31]=radial
__device__ __forceinline__ void edge_accum(float4 v, float* acc, float& nbh) {
    float x = v.x, y = v.y, z = v.z;
    float d2 = fmaxf(x * x + y * y + z * z, 1e-24f);
    float rinv = rsqrtf(d2);
    float r = d2 * rinv;

    float s1, c1;
    __sincosf(r * (PI_F / R_MAX_F), &s1, &c1);
    float cut = (r < R_MAX_F) ? 0.5f * (c1 + 1.0f) : 0.0f;
    nbh += cut;

    float ux = x * rinv, uy = y * rinv, uz = z * rinv;
    float x2 = ux * ux, y2 = uy * uy, z2 = uz * uz;

    acc[0] += uy;
    acc[1] += uz;
    acc[2] += ux;
    float xy = ux * uy;
    acc[3] += xy;
    acc[4] += uy * uz;
    acc[5] += ux * uz;
    acc[6] += x2;
    acc[7] += y2;
    acc[8] += z2;
    float t9  = fmaf(3.0f, x2, -y2);       // 3x²−y²
    acc[9]  += uy * t9;
    acc[10] += xy * uz;                     // xyz
    float t11 = fmaf(5.0f, z2, -1.0f);      // 5z²−1 (shared by 11,12,13)
    acc[11] += uy * t11;
    acc[12] += uz * (t11 - 2.0f);           // uz(5z²−3)
    acc[13] += ux * t11;
    acc[14] += uz * (x2 - y2);
    float w15 = fmaf(-3.0f, y2, x2);        // x²−3y²
    acc[15] += ux * w15;

    // radial: 1/r == rinv exactly, so pref needs no division
    float pref = cut * 0.5773502691896258f * rinv;
    float twoc = 2.0f * c1;
    float sk_prev = 0.0f;
    float sk = s1;
#pragma unroll
    for (int m = 0; m < 16; m++) {
        acc[16 + m] += pref * sk;
        float sk_next = fmaf(twoc, sk, -sk_prev);
        sk_prev = sk;
        sk = sk_next;
    }
}

// Gather: 4 threads per node, software-pipelined, quad shfl reduction,
// constant scaling applied once per node, single 128B store.
__global__ void __launch_bounds__(128) k_gather(const int* __restrict__ Z,
                                                float4* __restrict__ out4,
                                                int N) {
    int tid = threadIdx.x;
    int lane = tid & 3;
    int n = blockIdx.x * 32 + (tid >> 2);
    if (n >= N) return;

    int cnt = g_count[n];
    if (lane == 0) g_count[n] = 0;
    if (cnt > MAX_DEG) cnt = MAX_DEG;

    float acc[32];
#pragma unroll
    for (int k = 0; k < 32; k++) acc[k] = 0.0f;
    float nbh = 0.0f;

    const float4* ed = &g_edata[n << 6];

    int k = lane;
    bool va = (k < cnt), vb = (k + 4 < cnt);
    float4 a, b2;
    if (va) a = __ldg(&ed[k]);
    if (vb) b2 = __ldg(&ed[k + 4]);
    while (va) {
        int k2 = k + 8;
        bool vc = (k2 < cnt), vd = (k2 + 4 < cnt);
        float4 c, d;
        if (vc) c = __ldg(&ed[k2]);
        if (vd) d = __ldg(&ed[k2 + 4]);
        edge_accum(a, acc, nbh);
        if (vb) edge_accum(b2, acc, nbh);
        a = c; b2 = d; va = vc; vb = vd; k = k2;
    }

#pragma unroll
    for (int off = 2; off >= 1; off >>= 1) {
        nbh += __shfl_down_sync(0xFFFFFFFFu, nbh, off, 4);
#pragma unroll
        for (int q = 0; q < 32; q++)
            acc[q] += __shfl_down_sync(0xFFFFFFFFu, acc[q], off, 4);
    }

    if (lane == 0) {
        const float s3   = 1.7320508075688772f;
        const float s15  = 3.872983346207417f;
        const float s104 = 0.7905694150420949f;
        const float s64  = 0.6123724356957945f;
        const float s152 = 1.9364916731037085f;

        float fc = (float)cnt;
        float sph[16];
        sph[0]  = fc;
        sph[1]  = acc[0];
        sph[2]  = acc[1];
        sph[3]  = acc[2];
        sph[4]  = s3 * acc[3];
        sph[5]  = s3 * acc[4];
        sph[6]  = 0.5f * fmaf(3.0f, acc[8], -fc);
        sph[7]  = s3 * acc[5];
        sph[8]  = 0.5f * s3 * (acc[6] - acc[7]);
        sph[9]  = s104 * acc[9];
        sph[10] = s15 * acc[10];
        sph[11] = s64 * acc[11];
        sph[12] = 0.5f * acc[12];
        sph[13] = s64 * acc[13];
        sph[14] = s152 * acc[14];
        sph[15] = s104 * acc[15];

        float mask = (Z[n] != 0) ? 1.0f : 0.0f;
        float ps = ((nbh > 0.0f) ? 1.0f / nbh : 1.0f) * mask;

        float4* o = out4 + (size_t)n * 40 + 32;
#pragma unroll
        for (int q = 0; q < 4; q++)
            o[q] = make_float4(sph[4 * q] * ps, sph[4 * q + 1] * ps,
                               sph[4 * q + 2] * ps, sph[4 * q + 3] * ps);
#pragma unroll
        for (int q = 4; q < 8; q++)
            o[q] = make_float4(acc[4 * q] * mask, acc[4 * q + 1] * mask,
                               acc[4 * q + 2] * mask, acc[4 * q + 3] * mask);
    }
}

extern "C" void kernel_launch(void* const* d_in, const int* in_sizes, int n_in,
                              void* d_out, int out_size) {
    const float* dr  = (const float*)d_in[0];   // [E,3]
    const int*   Z   = (const int*)d_in[1];     // [N]
    const int*   idx = (const int*)d_in[2];     // [2,E]
    const float* emb = (const float*)d_in[3];   // [119,128]
    float* out = (float*)d_out;                 // [N,160]

    int E = in_sizes[2] / 2;
    int N = in_sizes[1];

    long total = (long)N * 32;
    long halfsz = (total + 1) / 2;
    int HB1 = (int)((halfsz + 2047) / 2048);
    int HB2 = (int)((total - halfsz + 2047) / 2048);
    int EB = (E + 255) / 256;

    k_emb<<<HB1, 256>>>(Z, (const float4*)emb, (float4*)out, N, 0);
    k_bucket<<<EB, 256>>>(dr, idx, E);
    k_emb<<<HB2, 256>>>(Z, (const float4*)emb, (float4*)out, N, 1);
    k_gather<<<(N + 31) / 32, 128>>>(Z, (float4*)out, N);
}

// round 16
// speedup vs baseline: 1.0006x; 1.0006x over previous
#include <cuda_runtime.h>
#include <math.h>

#define R_MAX_F 6.0f
#define PI_F 3.14159265358979323846f
#define MAX_N 50048
#define MAX_DEG 64

// Static scratch (alloc-free rule). g_count zero at module load; gather phase
// re-zeroes after reading. g_bar is a monotonic grid-barrier counter (grows by
// gridDim per call; work and output are identical every call).
__device__ int g_count[MAX_N];
__device__ float4 g_edata[MAX_N * MAX_DEG];   // 51 MB (ux,uy,uz,r) per edge
__device__ unsigned long long g_bar = 0ULL;

// Per-edge accumulate on normalized payload (ux,uy,uz,r) — R12-proven version
__device__ __forceinline__ void edge_accum(float4 v, float* acc, float& nbh) {
    const float s3   = 1.7320508075688772f;
    const float s15  = 3.872983346207417f;
    const float s104 = 0.7905694150420949f;
    const float s64  = 0.6123724356957945f;
    const float s152 = 1.9364916731037085f;

    float ux = v.x, uy = v.y, uz = v.z, r = v.w;

    float s1, c1;
    __sincosf(r * (PI_F / R_MAX_F), &s1, &c1);
    float cut = (r < R_MAX_F) ? 0.5f * (c1 + 1.0f) : 0.0f;
    nbh += cut;

    float ux2 = ux * ux, uy2 = uy * uy, uz2 = uz * uz;
    acc[1]  += uy;
    acc[2]  += uz;
    acc[3]  += ux;
    acc[4]  += s3 * ux * uy;
    acc[5]  += s3 * uy * uz;
    acc[6]  += 0.5f * (3.0f * uz2 - 1.0f);
    acc[7]  += s3 * ux * uz;
    acc[8]  += 0.5f * s3 * (ux2 - uy2);
    acc[9]  += s104 * uy * (3.0f * ux2 - uy2);
    acc[10] += s15 * ux * uy * uz;
    acc[11] += s64 * uy * (5.0f * uz2 - 1.0f);
    acc[12] += 0.5f * uz * (5.0f * uz2 - 3.0f);
    acc[13] += s64 * ux * (5.0f * uz2 - 1.0f);
    acc[14] += s152 * uz * (ux2 - uy2);
    acc[15] += s104 * ux * (ux2 - 3.0f * uy2);

    float pref = __fdividef(cut * 0.5773502691896258f, r);
    float twoc = 2.0f * c1;
    float sk_prev = 0.0f;
    float sk = s1;
#pragma unroll
    for (int m = 0; m < 16; m++) {
        acc[16 + m] += pref * sk;
        float sk_next = twoc * sk - sk_prev;
        sk_prev = sk;
        sk = sk_next;
    }
}

// Single persistent kernel: bucket -> emb copy -> grid barrier -> gather.
__global__ void __launch_bounds__(256) k_fused(const float* __restrict__ dr,
                                               const int* __restrict__ idx,
                                               const int* __restrict__ Z,
                                               const float4* __restrict__ emb4,
                                               float4* __restrict__ out4,
                                               int E, int N) {
    int tid = threadIdx.x;
    int G = gridDim.x;

    // ---- Phase 1a: bucket (one edge per thread-iteration, max TLP) ----
    for (int e = blockIdx.x * 256 + tid; e < E; e += G * 256) {
        int i = idx[e];
        int j = idx[E + e];
        if (i == j) continue;
        float x = dr[3 * e + 0];
        float y = dr[3 * e + 1];
        float z = dr[3 * e + 2];
        float d2 = fmaxf(x * x + y * y + z * z, 1e-24f);
        float rinv = rsqrtf(d2);
        float r = d2 * rinv;
        int slot = atomicAdd(&g_count[i], 1);
        if (slot < MAX_DEG)
            g_edata[(i << 6) + slot] =
                make_float4(x * rinv, y * rinv, z * rinv, r);
    }

    // ---- Phase 1b: embedding copy (absorbs bucket stragglers) ----
    {
        long total = (long)N * 32;
        for (long lin = (long)blockIdx.x * 256 + tid; lin < total;
             lin += (long)G * 256) {
            int n = (int)(lin >> 5);
            int c = (int)(lin & 31);
            int z = Z[n];
            float4 v = make_float4(0.f, 0.f, 0.f, 0.f);
            if (z != 0) v = emb4[z * 32 + c];
            out4[(size_t)n * 40 + c] = v;
        }
    }

    // ---- Grid barrier (monotonic counter; release/acquire fences) ----
    __shared__ unsigned long long s_tgt;
    __threadfence();                 // publish phase-1 stores
    __syncthreads();
    if (tid == 0) {
        unsigned long long old = atomicAdd(&g_bar, 1ULL);
        s_tgt = old - (old % (unsigned long long)G) + (unsigned long long)G;
    }
    __syncthreads();
    if (tid == 0) {
        unsigned long long tgt = s_tgt;
        while (*(volatile unsigned long long*)&g_bar < tgt)
            __nanosleep(128);
    }
    __syncthreads();
    __threadfence();                 // acquire phase-1 stores

    // ---- Phase 2: gather, 4 threads per node, 64 nodes per block-iter ----
    int lane = tid & 3;
    int nlocal = tid >> 2;
    for (long base = (long)blockIdx.x * 64; base < N; base += (long)G * 64) {
        int n = (int)base + nlocal;
        if (n >= N) break;

        int cnt = g_count[n];
        if (lane == 0) g_count[n] = 0;
        if (cnt > MAX_DEG) cnt = MAX_DEG;

        float acc[32];
#pragma unroll
        for (int k = 0; k < 32; k++) acc[k] = 0.0f;
        float nbh = 0.0f;

        const float4* ed = &g_edata[n << 6];

        int k = lane;
        bool va = (k < cnt), vb = (k + 4 < cnt);
        float4 a, b2;
        if (va) a = __ldg(&ed[k]);
        if (vb) b2 = __ldg(&ed[k + 4]);
        while (va) {
            int k2 = k + 8;
            bool vc = (k2 < cnt), vd = (k2 + 4 < cnt);
            float4 c, d;
            if (vc) c = __ldg(&ed[k2]);
            if (vd) d = __ldg(&ed[k2 + 4]);
            edge_accum(a, acc, nbh);
            if (vb) edge_accum(b2, acc, nbh);
            a = c; b2 = d; va = vc; vb = vd; k = k2;
        }

#pragma unroll
        for (int off = 2; off >= 1; off >>= 1) {
            nbh += __shfl_down_sync(0xFFFFFFFFu, nbh, off, 4);
#pragma unroll
            for (int q = 1; q < 32; q++)
                acc[q] += __shfl_down_sync(0xFFFFFFFFu, acc[q], off, 4);
        }
        acc[0] = (float)cnt;

        if (lane == 0) {
            float mask = (Z[n] != 0) ? 1.0f : 0.0f;
            float ps = ((nbh > 0.0f) ? 1.0f / nbh : 1.0f) * mask;

            float4* o = out4 + (size_t)n * 40 + 32;
#pragma unroll
            for (int q = 0; q < 4; q++)
                o[q] = make_float4(acc[4 * q] * ps, acc[4 * q + 1] * ps,
                                   acc[4 * q + 2] * ps, acc[4 * q + 3] * ps);
#pragma unroll
            for (int q = 4; q < 8; q++)
                o[q] = make_float4(acc[4 * q] * mask, acc[4 * q + 1] * mask,
                                   acc[4 * q + 2] * mask, acc[4 * q + 3] * mask);
        }
    }
}

extern "C" void kernel_launch(void* const* d_in, const int* in_sizes, int n_in,
                              void* d_out, int out_size) {
    const float* dr  = (const float*)d_in[0];   // [E,3]
    const int*   Z   = (const int*)d_in[1];     // [N]
    const int*   idx = (const int*)d_in[2];     // [2,E]
    const float* emb = (const float*)d_in[3];   // [119,128]
    float* out = (float*)d_out;                 // [N,160]

    int E = in_sizes[2] / 2;
    int N = in_sizes[1];

    // Exactly-resident grid so the device-side barrier cannot deadlock.
    int dev = 0, sms = 0, per = 0;
    cudaGetDevice(&dev);
    cudaDeviceGetAttribute(&sms, cudaDevAttrMultiProcessorCount, dev);
    cudaOccupancyMaxActiveBlocksPerMultiprocessor(&per, k_fused, 256, 0);
    if (per < 1) per = 1;
    int G = sms * per;

    k_fused<<<G, 256>>>(dr, idx, Z, (const float4*)emb, (float4*)out, E, N);
}

// round 17
// speedup vs baseline: 1.0349x; 1.0343x over previous
#include <cuda_runtime.h>
#include <math.h>

#define R_MAX_F 6.0f
#define PI_F 3.14159265358979323846f
#define MAX_N 50048
#define MAX_DEG 64

typedef unsigned long long u64;

// Static scratch (alloc-free rule). g_count zero at module load; k_gather
// re-zeroes after reading, so every execution starts from zero.
__device__ int g_count[MAX_N];
__device__ float4 g_edata[MAX_N * MAX_DEG];   // 51 MB (ux,uy,uz,r) per edge

// ---- packed f32x2 helpers (Blackwell sm_103a) ----
__device__ __forceinline__ u64 pk2(float lo, float hi) {
    u64 r; asm("mov.b64 %0, {%1, %2};" : "=l"(r) : "f"(lo), "f"(hi)); return r;
}
__device__ __forceinline__ void upk2(u64 v, float& lo, float& hi) {
    asm("mov.b64 {%0, %1}, %2;" : "=f"(lo), "=f"(hi) : "l"(v));
}
__device__ __forceinline__ u64 fma2_(u64 a, u64 b, u64 c) {
    u64 d; asm("fma.rn.f32x2 %0, %1, %2, %3;" : "=l"(d) : "l"(a), "l"(b), "l"(c)); return d;
}
__device__ __forceinline__ u64 add2_(u64 a, u64 b) {
    u64 d; asm("add.rn.f32x2 %0, %1, %2;" : "=l"(d) : "l"(a), "l"(b)); return d;
}
__device__ __forceinline__ u64 mul2_(u64 a, u64 b) {
    u64 d; asm("mul.rn.f32x2 %0, %1, %2;" : "=l"(d) : "l"(a), "l"(b)); return d;
}
__device__ __forceinline__ u64 neg2_(u64 a) { return a ^ 0x8000000080000000ULL; }

#define C2P  0x4000000040000000ULL   // ( 2.0f,  2.0f)
#define C3P  0x4040000040400000ULL   // ( 3.0f,  3.0f)
#define C5P  0x40A0000040A00000ULL   // ( 5.0f,  5.0f)
#define CM1P 0xBF800000BF800000ULL   // (-1.0f, -1.0f)
#define CM2P 0xC0000000C0000000ULL   // (-2.0f, -2.0f)
#define CM3P 0xC0400000C0400000ULL   // (-3.0f, -3.0f)

// Kernel 1: bucket — ONE edge per thread, normalized payload (R13-proven).
__global__ void __launch_bounds__(256) k_bucket(const float* __restrict__ dr,
                                                const int* __restrict__ idx,
                                                int E) {
    int e = blockIdx.x * 256 + threadIdx.x;
    if (e >= E) return;
    int i = idx[e];
    int j = idx[E + e];
    if (i == j) return;

    float x = dr[3 * e + 0];
    float y = dr[3 * e + 1];
    float z = dr[3 * e + 2];
    float d2 = fmaxf(x * x + y * y + z * z, 1e-24f);
    float rinv = rsqrtf(d2);
    float r = d2 * rinv;

    int slot = atomicAdd(&g_count[i], 1);
    if (slot < MAX_DEG)
        g_edata[(i << 6) + slot] =
            make_float4(x * rinv, y * rinv, z * rinv, r);
}

// Packed pair accumulate: edges A (lo lane) and B (hi lane).
// acc[1..15] = raw sph moments, acc[0] = Σx(x²−3y²), acc[16..31] = radial.
__device__ __forceinline__ void pair_accum(float4 A, float4 B,
                                           u64* acc, float& nbh) {
    // scalar heads
    float s1a, c1a, s1b, c1b;
    __sincosf(A.w * (PI_F / R_MAX_F), &s1a, &c1a);
    __sincosf(B.w * (PI_F / R_MAX_F), &s1b, &c1b);
    float cuta = (A.w < R_MAX_F) ? fmaf(0.5f, c1a, 0.5f) : 0.0f;
    float cutb = (B.w < R_MAX_F) ? fmaf(0.5f, c1b, 0.5f) : 0.0f;
    nbh += cuta + cutb;
    float prefa = __fdividef(cuta * 0.5773502691896258f, A.w);
    float prefb = __fdividef(cutb * 0.5773502691896258f, B.w);

    u64 ux = pk2(A.x, B.x);
    u64 uy = pk2(A.y, B.y);
    u64 uz = pk2(A.z, B.z);

    // moments
    acc[1] = add2_(acc[1], uy);
    acc[2] = add2_(acc[2], uz);
    acc[3] = add2_(acc[3], ux);
    acc[4] = fma2_(ux, uy, acc[4]);           // Σxy
    acc[5] = fma2_(uy, uz, acc[5]);           // Σyz
    acc[6] = fma2_(ux, uz, acc[6]);           // Σxz
    u64 x2 = mul2_(ux, ux);
    u64 y2 = mul2_(uy, uy);
    u64 z2 = mul2_(uz, uz);
    acc[7] = add2_(acc[7], x2);
    acc[8] = add2_(acc[8], y2);
    acc[9] = add2_(acc[9], z2);
    u64 ny2 = neg2_(y2);
    u64 t9  = fma2_(C3P, x2, ny2);            // 3x²−y²
    acc[10] = fma2_(uy, t9, acc[10]);
    u64 xy = mul2_(ux, uy);
    acc[11] = fma2_(xy, uz, acc[11]);         // Σxyz
    u64 t11 = fma2_(C5P, z2, CM1P);           // 5z²−1
    acc[12] = fma2_(uy, t11, acc[12]);
    u64 t13 = add2_(t11, CM2P);               // 5z²−3
    acc[13] = fma2_(uz, t13, acc[13]);
    acc[14] = fma2_(ux, t11, acc[14]);
    u64 t15 = add2_(x2, ny2);                 // x²−y²
    acc[15] = fma2_(uz, t15, acc[15]);
    u64 w15 = fma2_(CM3P, y2, x2);            // x²−3y²
    acc[0] = fma2_(ux, w15, acc[0]);

    // radial: acc[16+m] += pref·s_{m+1}; state p=s_{m-1}, q=−s_m
    u64 twocp = mul2_(pk2(c1a, c1b), C2P);
    u64 q = neg2_(pk2(s1a, s1b));
    u64 p = 0ULL;
    u64 npref = neg2_(pk2(prefa, prefb));
#pragma unroll
    for (int m = 0; m < 16; m++) {
        acc[16 + m] = fma2_(npref, q, acc[16 + m]);   // += pref·s_{m+1}
        u64 qn = fma2_(twocp, q, p);                  // −s_{m+2}
        p = neg2_(q);                                 // s_{m+1}
        q = qn;
    }
}

// Kernel 2: blocks [0,GB): 4 threads/node, packed-pair pipelined gather.
// Blocks [GB,GB+NB): coalesced embedding copy.
__global__ void __launch_bounds__(128) k_gather(const int* __restrict__ Z,
                                                const float4* __restrict__ emb4,
                                                float4* __restrict__ out4,
                                                int N, int GB) {
    int tid = threadIdx.x;
    int b = blockIdx.x;

    if (b >= GB) {
        long base = (long)(b - GB) * 2048 + tid;
        long total = (long)N * 32;
#pragma unroll
        for (int k = 0; k < 16; k++) {
            long lin = base + (long)k * 128;
            if (lin < total) {
                int n = (int)(lin >> 5);
                int c = (int)(lin & 31);
                int z = Z[n];
                float4 v = make_float4(0.f, 0.f, 0.f, 0.f);
                if (z != 0) v = emb4[z * 32 + c];
                out4[(size_t)n * 40 + c] = v;
            }
        }
        return;
    }

    int lane = tid & 3;
    int n = b * 32 + (tid >> 2);
    if (n >= N) return;

    int cnt = g_count[n];
    if (lane == 0) g_count[n] = 0;
    if (cnt > MAX_DEG) cnt = MAX_DEG;

    u64 acc[32];
#pragma unroll
    for (int k = 0; k < 32; k++) acc[k] = 0ULL;
    float nbh = 0.0f;

    const float4* ed = &g_edata[n << 6];
    const float4 NEUT = make_float4(0.f, 0.f, 0.f, 8.0f);  // cut=0, u=0

    int k = lane;
    float4 a = (k < cnt) ? __ldg(&ed[k]) : NEUT;
    float4 b2 = (k + 4 < cnt) ? __ldg(&ed[k + 4]) : NEUT;
    while (k < cnt) {
        int k2 = k + 8;
        float4 c = (k2 < cnt) ? __ldg(&ed[k2]) : NEUT;
        float4 d = (k2 + 4 < cnt) ? __ldg(&ed[k2 + 4]) : NEUT;
        pair_accum(a, b2, acc, nbh);
        a = c; b2 = d; k = k2;
    }

    // collapse packed halves to scalars
    float accs[32];
#pragma unroll
    for (int q = 0; q < 32; q++) {
        float lo, hi;
        upk2(acc[q], lo, hi);
        accs[q] = lo + hi;
    }

    // quad reduction (width 4)
#pragma unroll
    for (int off = 2; off >= 1; off >>= 1) {
        nbh += __shfl_down_sync(0xFFFFFFFFu, nbh, off, 4);
#pragma unroll
        for (int q = 0; q < 32; q++)
            accs[q] += __shfl_down_sync(0xFFFFFFFFu, accs[q], off, 4);
    }

    if (lane == 0) {
        const float s3   = 1.7320508075688772f;
        const float s15  = 3.872983346207417f;
        const float s104 = 0.7905694150420949f;
        const float s64  = 0.6123724356957945f;
        const float s152 = 1.9364916731037085f;

        float fc = (float)cnt;
        float sph[16];
        sph[0]  = fc;
        sph[1]  = accs[1];
        sph[2]  = accs[2];
        sph[3]  = accs[3];
        sph[4]  = s3 * accs[4];
        sph[5]  = s3 * accs[5];
        sph[6]  = 0.5f * fmaf(3.0f, accs[9], -fc);
        sph[7]  = s3 * accs[6];
        sph[8]  = 0.5f * s3 * (accs[7] - accs[8]);
        sph[9]  = s104 * accs[10];
        sph[10] = s15 * accs[11];
        sph[11] = s64 * accs[12];
        sph[12] = 0.5f * accs[13];
        sph[13] = s64 * accs[14];
        sph[14] = s152 * accs[15];
        sph[15] = s104 * accs[0];

        float mask = (Z[n] != 0) ? 1.0f : 0.0f;
        float ps = ((nbh > 0.0f) ? 1.0f / nbh : 1.0f) * mask;

        float4* o = out4 + (size_t)n * 40 + 32;
#pragma unroll
        for (int q = 0; q < 4; q++)
            o[q] = make_float4(sph[4 * q] * ps, sph[4 * q + 1] * ps,
                               sph[4 * q + 2] * ps, sph[4 * q + 3] * ps);
#pragma unroll
        for (int q = 4; q < 8; q++)
            o[q] = make_float4(accs[4 * q] * mask, accs[4 * q + 1] * mask,
                               accs[4 * q + 2] * mask, accs[4 * q + 3] * mask);
    }
}

extern "C" void kernel_launch(void* const* d_in, const int* in_sizes, int n_in,
                              void* d_out, int out_size) {
    const float* dr  = (const float*)d_in[0];   // [E,3]
    const int*   Z   = (const int*)d_in[1];     // [N]
    const int*   idx = (const int*)d_in[2];     // [2,E]
    const float* emb = (const float*)d_in[3];   // [119,128]
    float* out = (float*)d_out;                 // [N,160]

    int E = in_sizes[2] / 2;
    int N = in_sizes[1];

    int EB = (E + 255) / 256;
    k_bucket<<<EB, 256>>>(dr, idx, E);

    int GB = (N + 31) / 32;                              // gather node blocks
    int NB = (int)(((long)N * 32 + 2047) / 2048);        // emb copy blocks
    k_gather<<<GB + NB, 128>>>(Z, (const float4*)emb, (float4*)out, N, GB);
}